// round 17
// baseline (speedup 1.0000x reference)
#include <cuda_runtime.h>
#include <cuda_fp16.h>
#include <float.h>
#include <stdint.h>

// Fixed problem shape
#define KC      512
#define DC      64
#define HWC     4096
#define NC      131072
#define TPB     256         // 8 warps
#define PIX     128         // pixels per tile
#define NTILES  (NC/PIX)    // 1024
#define GRIDP   256         // 2 CTAs/SM; dynamic tile stealing
#define EPITCH  72          // fp16 codebook pitch (144B rows; LDSM conflict-free)
#define FPITCH  66          // fp32 latent pitch

// smem layout (bytes)
#define OFF_ECB 0                           // half [512][72]   73728
#define OFF_F32 (OFF_ECB + KC*EPITCH*2)     // fp32 [128][66]   33792
#define OFF_EN  (OFF_F32 + PIX*FPITCH*4)    // float[512]        2048
#define OFF_FN  (OFF_EN + KC*4)             // float[128]         512
#define OFF_SLK (OFF_FN + PIX*4)            // float[128]         512
#define OFF_BST (OFF_SLK + PIX*4)           // u64  [128]        1024 (red overlays)
#define OFF_FLG (OFF_BST + PIX*8)           // int  [128]         512
#define OFF_CNT (OFF_FLG + PIX*4)           // int + pad           16
#define SMEM_BYTES (OFF_CNT + 16)           // 112144 -> 2 CTAs/SM

__device__ float    g_part[NTILES];
__device__ unsigned g_done;
__device__ unsigned g_tile;

typedef unsigned long long u64;

__device__ __forceinline__ void mma_fp16(float c[4], const unsigned a[4],
                                         unsigned b0, unsigned b1) {
    asm volatile(
        "mma.sync.aligned.m16n8k16.row.col.f32.f16.f16.f32 "
        "{%0,%1,%2,%3}, {%4,%5,%6,%7}, {%8,%9}, {%0,%1,%2,%3};"
        : "+f"(c[0]), "+f"(c[1]), "+f"(c[2]), "+f"(c[3])
        : "r"(a[0]), "r"(a[1]), "r"(a[2]), "r"(a[3]), "r"(b0), "r"(b1));
}

__device__ __forceinline__ void ldsm_x4(unsigned& d0, unsigned& d1,
                                        unsigned& d2, unsigned& d3,
                                        unsigned addr) {
    asm volatile(
        "ldmatrix.sync.aligned.m8n8.x4.shared.b16 {%0,%1,%2,%3}, [%4];"
        : "=r"(d0), "=r"(d1), "=r"(d2), "=r"(d3) : "r"(addr));
}

__device__ __forceinline__ unsigned pack_hf2(float x, float y) {
    __half2 h = __floats2half2_rn(x, y);     // low = x, high = y
    return *reinterpret_cast<unsigned*>(&h);
}

// exact reference-arithmetic distance for (pixel fr, code k)
__device__ __forceinline__ float exact_dist(const float* fr, const float* emb,
                                            float fn, float en, int k) {
    const float4* er4 = (const float4*)(emb + (size_t)k * DC);
    float dot = 0.0f;
    #pragma unroll
    for (int q = 0; q < 16; ++q) {
        float4 ev = __ldg(er4 + q);
        dot = fmaf(fr[4 * q + 0], ev.x, dot);
        dot = fmaf(fr[4 * q + 1], ev.y, dot);
        dot = fmaf(fr[4 * q + 2], ev.z, dot);
        dot = fmaf(fr[4 * q + 3], ev.w, dot);
    }
    return __fsub_rn(__fadd_rn(fn, en), __fmul_rn(2.0f, dot));
}

__device__ __forceinline__ u64 dist_key(float r, int k) {
    unsigned rb = __float_as_uint(r);
    rb ^= (rb >> 31) ? 0xFFFFFFFFu : 0x80000000u;   // order-preserving
    return ((u64)rb << 32) | (unsigned)k;
}

__device__ __forceinline__ u64 u64min(u64 a, u64 b) { return (a < b) ? a : b; }

__global__ __launch_bounds__(TPB, 2)
void vq_kernel(const float* __restrict__ latents,
               const float* __restrict__ embedding,
               float* __restrict__ out,
               float* __restrict__ loss_out) {
    extern __shared__ char smem[];
    __half* Ecb = (__half*)(smem + OFF_ECB);
    float* F32  = (float*)(smem + OFF_F32);
    float* enS  = (float*)(smem + OFF_EN);
    float* fnS  = (float*)(smem + OFF_FN);
    float* slkS = (float*)(smem + OFF_SLK);
    u64*   bestS = (u64*)(smem + OFF_BST);
    int*   flg  = (int*)(smem + OFF_FLG);
    int*   fcnt = (int*)(smem + OFF_CNT);
    float* red  = (float*)(smem + OFF_BST);   // overlay after bestS dead

    const int tid  = threadIdx.x;
    const int wid  = tid >> 5;
    const int lane = tid & 31;
    const int g    = lane >> 2;
    const int tig  = lane & 3;
    const int px   = tid & (PIX - 1);
    const int hh   = tid >> 7;

    unsigned ecbA;
    asm("{ .reg .u64 t; cvta.to.shared.u64 t, %1; cvt.u32.u64 %0, t; }"
        : "=r"(ecbA) : "l"(Ecb));
    const unsigned rowoff = (unsigned)((lane & 7) * (EPITCH * 2) + (lane >> 3) * 16);

    // ---- once per CTA: fp16 codebook + exact reference enorm ----
    for (int i = tid; i < KC * DC; i += TPB) {
        int k = i >> 6, d = i & 63;
        Ecb[k * EPITCH + d] = __float2half_rn(embedding[i]);
    }
    #pragma unroll
    for (int kk = 0; kk < 2; ++kk) {
        int k = tid + kk * TPB;
        const float* er = embedding + (size_t)k * DC;
        float s = 0.0f;
        #pragma unroll
        for (int d = 0; d < DC; ++d)
            s = __fadd_rn(s, __fmul_rn(er[d], er[d]));
        enS[k] = s;
    }
    __syncthreads();

    __shared__ int s_tile;

    while (true) {
        if (tid == 0) s_tile = (int)atomicAdd(&g_tile, 1u);
        __syncthreads();
        const int tile = s_tile;
        if (tile >= NTILES) break;

        const int P  = tile * PIX + px;
        const int b  = P >> 12;
        const int hw = P & (HWC - 1);
        const float* lat = latents + (size_t)b * DC * HWC + hw;

        // ---- phase 0: stage latents (all 256 threads, half-pixel each) ----
        {
            float* fr = F32 + px * FPITCH;
            #pragma unroll
            for (int j = 0; j < 32; ++j) {
                int d = hh * 32 + j;
                fr[d] = lat[d * HWC];
            }
            if (tid == 0) *fcnt = 0;
        }
        __syncthreads();

        // ---- A fragments (fp16 from smem) + fnorm/slack ----
        const int r0 = wid * 16 + g;
        const int r1 = r0 + 8;
        unsigned afr[4][4];
        #pragma unroll
        for (int ks = 0; ks < 4; ++ks) {
            float2 p0 = *(const float2*)(F32 + r0 * FPITCH + 16 * ks + 2 * tig);
            float2 p1 = *(const float2*)(F32 + r1 * FPITCH + 16 * ks + 2 * tig);
            float2 p2 = *(const float2*)(F32 + r0 * FPITCH + 16 * ks + 8 + 2 * tig);
            float2 p3 = *(const float2*)(F32 + r1 * FPITCH + 16 * ks + 8 + 2 * tig);
            afr[ks][0] = pack_hf2(p0.x, p0.y);
            afr[ks][1] = pack_hf2(p1.x, p1.y);
            afr[ks][2] = pack_hf2(p2.x, p2.y);
            afr[ks][3] = pack_hf2(p3.x, p3.y);
        }
        if (tid < PIX) {
            const float* fr = F32 + tid * FPITCH;
            float fn = 0.0f, bndB = 0.0f, bndA = 0.0f;
            #pragma unroll
            for (int d = 0; d < DC; ++d) {
                float f = fr[d];
                fn = __fadd_rn(fn, __fmul_rn(f, f));
                bndB += fabsf(f);
                float fh = __half2float(__float2half_rn(f));
                bndA += fabsf(f - fh);
            }
            fnS[tid]  = fn;
            float bnd = bndB * 9.6e-7f + bndA * 1.96e-3f;
            slkS[tid] = fmaf(5.0f, bnd, 4.0e-5f);
        }
        __syncthreads();

        // ---- single fp16 GEMM pass with (min, argmin, 2nd-min) tracking ----
        float rv0 = FLT_MAX, r20 = FLT_MAX;
        float rv1 = FLT_MAX, r21 = FLT_MAX;
        int   rk0 = 0, rk1 = 0;

        #pragma unroll 4
        for (int nb = 0; nb < KC / 8; ++nb) {
            const int cb = nb * 8;
            const unsigned baddr = ecbA + (unsigned)cb * (EPITCH * 2) + rowoff;
            unsigned b0, b1, b2, b3, b4, b5, b6, b7;
            ldsm_x4(b0, b1, b2, b3, baddr);
            ldsm_x4(b4, b5, b6, b7, baddr + 64);
            float c[4] = {0.f, 0.f, 0.f, 0.f};
            mma_fp16(c, afr[0], b0, b1);
            mma_fp16(c, afr[1], b2, b3);
            mma_fp16(c, afr[2], b4, b5);
            mma_fp16(c, afr[3], b6, b7);
            const int k0 = cb + 2 * tig;
            float en0 = enS[k0];
            float en1 = enS[k0 + 1];
            float s0 = fmaf(-2.0f, c[0], en0);
            float s1 = fmaf(-2.0f, c[1], en1);
            float s2 = fmaf(-2.0f, c[2], en0);
            float s3 = fmaf(-2.0f, c[3], en1);
            // pixel slot 0
            {
                float m = fminf(s0, s1), x = fmaxf(s0, s1);
                int   km = (s1 < s0) ? (k0 + 1) : k0;      // tie -> smaller k
                r20 = fminf(r20, fminf(x, fmaxf(rv0, m)));
                rk0 = (m < rv0) ? km : rk0;                // tie -> earlier (smaller) k
                rv0 = fminf(m, rv0);
            }
            // pixel slot 1
            {
                float m = fminf(s2, s3), x = fmaxf(s2, s3);
                int   km = (s3 < s2) ? (k0 + 1) : k0;
                r21 = fminf(r21, fminf(x, fmaxf(rv1, m)));
                rk1 = (m < rv1) ? km : rk1;
                rv1 = fminf(m, rv1);
            }
        }

        // merge over the 4 owning threads (lanes tig=0..3): v1, v2, argmin-key
        #pragma unroll
        for (int slot = 0; slot < 2; ++slot) {
            float rv = slot ? rv1 : rv0;
            float r2 = slot ? r21 : r20;
            int   rk = slot ? rk1 : rk0;
            int   row = slot ? r1 : r0;

            u64 key = dist_key(rv, rk);
            key = u64min(key, __shfl_xor_sync(0xffffffffu, key, 1));
            key = u64min(key, __shfl_xor_sync(0xffffffffu, key, 2));

            float o   = __shfl_xor_sync(0xffffffffu, rv, 1);
            float lo  = fminf(rv, o), hi = fmaxf(rv, o);
            float lo2 = __shfl_xor_sync(0xffffffffu, lo, 2);
            float hi2 = __shfl_xor_sync(0xffffffffu, hi, 2);
            float v1g = fminf(lo, lo2);
            float v2g = fminf(fmaxf(lo, lo2), fminf(hi, hi2));
            float r2o = fminf(r2, __shfl_xor_sync(0xffffffffu, r2, 1));
            r2o = fminf(r2o, __shfl_xor_sync(0xffffffffu, r2o, 2));
            v2g = fminf(v2g, r2o);

            if (tig == 0) {
                if (v2g - v1g > slkS[row]) {
                    bestS[row] = key;                     // certified winner
                } else {
                    bestS[row] = 0xFFFFFFFFFFFFFFFFull;   // needs exact scan
                    int i = atomicAdd(fcnt, 1);
                    flg[i] = row;
                }
            }
        }
        __syncthreads();

        // ---- fallback: CTA-wide exact scan for uncertified pixels ----
        {
            const int nf = *fcnt;
            for (int j = 0; j < nf; ++j) {
                const int pix = flg[j];
                const float fn = fnS[pix];
                const float* fr = F32 + pix * FPITCH;     // broadcast reads
                for (int k = tid; k < KC; k += TPB) {
                    float r = exact_dist(fr, embedding, fn, enS[k], k);
                    atomicMin(&bestS[pix], dist_key(r, k));  // value, then min k
                }
            }
        }
        __syncthreads();

        // ---- epilogue: all 256 threads (half pixel each) ----
        float ldist = 0.0f;
        {
            const int bestk = (int)(unsigned)(bestS[px] & 0xFFFFFFFFull);
            const float* fr = F32 + px * FPITCH + hh * 32;
            float* outp = out + (size_t)b * DC * HWC + hw + (size_t)(hh * 32) * HWC;
            const float4* er4 = (const float4*)(embedding + (size_t)bestk * DC + hh * 32);
            #pragma unroll
            for (int q = 0; q < 8; ++q) {
                float4 ev = __ldg(er4 + q);
                float f0 = fr[4 * q + 0], f1 = fr[4 * q + 1];
                float f2 = fr[4 * q + 2], f3 = fr[4 * q + 3];
                float d0 = __fsub_rn(ev.x, f0);
                float d1 = __fsub_rn(ev.y, f1);
                float d2 = __fsub_rn(ev.z, f2);
                float d3 = __fsub_rn(ev.w, f3);
                ldist = __fadd_rn(ldist, __fmul_rn(d0, d0));
                ldist = __fadd_rn(ldist, __fmul_rn(d1, d1));
                ldist = __fadd_rn(ldist, __fmul_rn(d2, d2));
                ldist = __fadd_rn(ldist, __fmul_rn(d3, d3));
                outp[(4 * q + 0) * HWC] = __fadd_rn(f0, d0);
                outp[(4 * q + 1) * HWC] = __fadd_rn(f1, d1);
                outp[(4 * q + 2) * HWC] = __fadd_rn(f2, d2);
                outp[(4 * q + 3) * HWC] = __fadd_rn(f3, d3);
            }
        }
        __syncthreads();            // bestS dead; red overlay safe

        // ---- per-tile deterministic tree reduce -> g_part[tile] ----
        red[tid] = ldist;
        __syncthreads();
        #pragma unroll
        for (int s = TPB / 2; s > 0; s >>= 1) {
            if (tid < s) red[tid] += red[tid + s];
            __syncthreads();
        }
        if (tid == 0) g_part[tile] = red[0];
        __syncthreads();
    }

    // ---- grid finalize ----
    __shared__ unsigned s_last;
    __threadfence();
    if (tid == 0) s_last = (atomicAdd(&g_done, 1u) == GRIDP - 1u);
    __syncthreads();

    if (s_last) {
        red[tid] = (g_part[tid] + g_part[tid + 256])
                 + (g_part[tid + 512] + g_part[tid + 768]);
        __syncthreads();
        #pragma unroll
        for (int s = TPB / 2; s > 0; s >>= 1) {
            if (tid < s) red[tid] += red[tid + s];
            __syncthreads();
        }
        if (tid == 0) {
            float m = red[0] / 8388608.0f;                   // exact /2^23
            *loss_out = __fadd_rn(__fmul_rn(m, 0.25f), m);   // fl(0.25m)+m
            g_done = 0;
            g_tile = 0;
        }
    }
}

extern "C" void kernel_launch(void* const* d_in, const int* in_sizes, int n_in,
                              void* d_out, int out_size) {
    const float* latents   = (const float*)d_in[0];
    const float* embedding = (const float*)d_in[1];
    float* out  = (float*)d_out;
    float* loss = out + (out_size - 1);

    cudaFuncSetAttribute(vq_kernel, cudaFuncAttributeMaxDynamicSharedMemorySize, SMEM_BYTES);
    vq_kernel<<<GRIDP, TPB, SMEM_BYTES>>>(latents, embedding, out, loss);
}